// round 16
// baseline (speedup 1.0000x reference)
#include <cuda_runtime.h>
#include <cuda_fp16.h>
#include <cstdint>
#include <cstddef>

// Problem constants
#define B_ROWS 8192
#define FEAT   7680
#define HID    512
#define KT1    (FEAT / 64)      // 120 K-slabs for GEMM1

// Scratch (allocation-free: __device__ globals)
__device__ __half g_feat16[(size_t)B_ROWS * FEAT];   // 126 MB (converted feat)
__device__ __half g_w1h[(size_t)HID * FEAT];         // 7.9 MB
__device__ __half g_w2h[(size_t)HID * HID];          // 0.5 MB
__device__ __half g_h1[(size_t)B_ROWS * HID];        // 8.4 MB
__device__ __half g_h2[(size_t)B_ROWS * HID];        // 8.4 MB
__device__ int    g_idx64;
__device__ int    g_flag[KT1 * 4];                   // sub-slab ready flags

// ---------------------------------------------------------------------------
// helpers
// ---------------------------------------------------------------------------
__device__ __forceinline__ void cp_async16(uint32_t smem_dst, const void* gptr) {
    asm volatile("cp.async.cg.shared.global [%0], [%1], 16;"
                 :: "r"(smem_dst), "l"(gptr));
}
__device__ __forceinline__ void cp_commit() {
    asm volatile("cp.async.commit_group;");
}
__device__ __forceinline__ uint32_t packf2(float x, float y) {
    __half2 h = __floats2half2_rn(x, y);
    return *(uint32_t*)&h;
}

// ---------------------------------------------------------------------------
// Init kernel: convert W1/W2 to fp16, reset sub-slab flags, detect idx dtype.
// Runs before gemm1 on the same stream -> ordering guaranteed.
// ---------------------------------------------------------------------------
__device__ __forceinline__ void cvt_range(const float4* __restrict__ in,
                                          uint2* __restrict__ out, int n4,
                                          int gtid, int stride)
{
    for (int i = gtid; i < n4; i += stride) {
        float4 v = in[i];
        uint2 u;
        u.x = packf2(v.x, v.y);
        u.y = packf2(v.z, v.w);
        out[i] = u;
    }
}

__global__ void init_kernel(const float4* __restrict__ w1, uint2* __restrict__ w1_o,
                            const float4* __restrict__ w2, uint2* __restrict__ w2_o,
                            const int* __restrict__ sidx_raw)
{
    const int gtid   = blockIdx.x * blockDim.x + threadIdx.x;
    const int stride = gridDim.x * blockDim.x;
    if (gtid < KT1 * 4) g_flag[gtid] = 0;
    if (gtid == 0) {
        // int64 values in [0,72) -> every odd 32-bit word is 0.
        int acc = 0;
        #pragma unroll
        for (int i = 0; i < 64; i++) acc |= sidx_raw[2 * i + 1];
        g_idx64 = (acc == 0) ? 1 : 0;
    }
    cvt_range(w1, w1_o, (HID * FEAT) / 4, gtid, stride);
    cvt_range(w2, w2_o, (HID * HID) / 4,  gtid, stride);
}

// ===========================================================================
// GEMM1 (fused converter): h1 = relu( feat @ W1h^T + b1 ), fp16 out.
// Grid = 148 CTAs:
//   CTAs 0..19   = converter role: stream feat fp32 -> g_feat16 fp16 in 480
//                  sub-slabs (2048 rows x 64 K-cols), publish g_flag[j].
//   CTAs 20..147 = MMA role: the exact R10/R15 roofline loop (CTA 128x256x64,
//                  warp tile 64x64, STG=4 cp.async), reading g_feat16, gated
//                  by a batched flag poll (one volatile L2 read per 4 kt).
// The 20 converter SMs were idle during GEMM1 anyway (128 MMA CTAs / 148 SMs)
// -> the 50us standalone convert pass becomes fully hidden.
// ===========================================================================
__global__ void __launch_bounds__(256, 1) gemm1_fused(
    const float* __restrict__ feat, const __half* __restrict__ Bw,
    const float* __restrict__ bias, __half* __restrict__ C)
{
    constexpr int BM = 128, BN = 256, BK = 64, STAGES = 4;
    constexpr int K = FEAT, N = HID, KT = KT1;
    constexpr int SKA = BK + 8;
    constexpr int SKB = BK + 8;
    constexpr int STAGE_H = BM * SKA + BN * SKB;
    constexpr int NCONV = 20;

    extern __shared__ __half smemh[];

    const int tid = threadIdx.x;

    // ---------------- converter role ----------------
    if (blockIdx.x < NCONV) {
        for (int j = blockIdx.x; j < KT * 4; j += NCONV) {
            const int s = j >> 2;          // K-slab
            const int q = j & 3;           // M-quarter (2048 rows)
            const size_t colbase = (size_t)s * 64;
            #pragma unroll 4
            for (int i = 0; i < 128; i++) {
                int t   = tid + i * 256;   // 0..32767
                int row = q * 2048 + (t >> 4);
                int c   = t & 15;
                float4 v = *((const float4*)(feat + (size_t)row * FEAT + colbase) + c);
                uint2 u;
                u.x = packf2(v.x, v.y);
                u.y = packf2(v.z, v.w);
                *(uint2*)(g_feat16 + (size_t)row * FEAT + colbase + c * 4) = u;
            }
            __threadfence();               // each thread's stores -> GPU scope
            __syncthreads();               // all threads fenced
            if (tid == 0) ((volatile int*)g_flag)[j] = 1;
            __syncthreads();
        }
        return;
    }

    // ---------------- MMA role (exact R10/R15 loop) ----------------
    const int b  = blockIdx.x - NCONV;     // 0..127
    const int m0 = (b >> 1) * BM;
    const int n0 = (b & 1) * BN;
    const int quarter = (b >> 1) >> 4;     // which 2048-row quarter

    const __half* A = g_feat16;

    const int warp = tid >> 5;
    const int lane = tid & 31;
    const int g    = lane >> 2;
    const int t4   = lane & 3;
    const int wm = (warp & 1) * 64;
    const int wn = (warp >> 1) * 64;

    float acc[4][8][4];
    #pragma unroll
    for (int i = 0; i < 4; i++)
        #pragma unroll
        for (int j = 0; j < 8; j++)
            #pragma unroll
            for (int k = 0; k < 4; k++) acc[i][j][k] = 0.f;

    int cleared = 0;   // slabs [0, cleared) known ready for our quarter
    auto wait_slabs = [&](int kn) {
        if (cleared > kn) return;
        int target = kn + 4;
        if (target > KT) target = KT;
        while (cleared < target) {
            if (((volatile int*)g_flag)[cleared * 4 + quarter] != 0) cleared++;
            else __nanosleep(100);
        }
        __threadfence();   // acquire: order flag read before cp.async reads
    };

    auto load_stage = [&](int s, int k0) {
        __half* As = smemh + s * STAGE_H;
        __half* Bs = As + BM * SKA;
        #pragma unroll
        for (int i = 0; i < 4; i++) {
            int q = tid + i * 256;
            int row = q >> 3, c = q & 7;
            cp_async16((uint32_t)__cvta_generic_to_shared(As + row * SKA + c * 8),
                       A + (size_t)(m0 + row) * K + k0 + c * 8);
        }
        #pragma unroll
        for (int i = 0; i < 8; i++) {
            int q = tid + i * 256;
            int row = q >> 3, c = q & 7;
            cp_async16((uint32_t)__cvta_generic_to_shared(Bs + row * SKB + c * 8),
                       Bw + (size_t)(n0 + row) * K + k0 + c * 8);
        }
    };

    #pragma unroll
    for (int s = 0; s < STAGES - 1; s++) {
        wait_slabs(s);
        load_stage(s, s * BK);
        cp_commit();
    }

    int buf = 0;
    for (int kt = 0; kt < KT; kt++) {
        asm volatile("cp.async.wait_group %0;" :: "n"(STAGES - 2));
        __syncthreads();

        int kn = kt + STAGES - 1;
        if (kn < KT) {
            wait_slabs(kn);
            load_stage(kn % STAGES, kn * BK);
        }
        cp_commit();

        const __half* As = smemh + buf * STAGE_H;
        const __half* Bs = As + BM * SKA;

        #pragma unroll
        for (int kk = 0; kk < BK / 16; kk++) {
            uint32_t bfr[8][2];
            #pragma unroll
            for (int ni = 0; ni < 8; ni++) {
                const __half* bp = Bs + (wn + ni * 8 + g) * SKB + kk * 16 + t4 * 2;
                bfr[ni][0] = *(const uint32_t*)bp;
                bfr[ni][1] = *(const uint32_t*)(bp + 8);
            }
            #pragma unroll
            for (int mi = 0; mi < 4; mi++) {
                const __half* ap  = As + (wm + mi * 16 + g) * SKA + kk * 16 + t4 * 2;
                const __half* ap8 = ap + 8 * SKA;
                uint32_t a0 = *(const uint32_t*)ap;
                uint32_t a1 = *(const uint32_t*)ap8;
                uint32_t a2 = *(const uint32_t*)(ap + 8);
                uint32_t a3 = *(const uint32_t*)(ap8 + 8);
                #pragma unroll
                for (int ni = 0; ni < 8; ni++) {
                    float* d = acc[mi][ni];
                    asm volatile(
                        "mma.sync.aligned.m16n8k16.row.col.f32.f16.f16.f32 "
                        "{%0,%1,%2,%3}, {%4,%5,%6,%7}, {%8,%9}, {%0,%1,%2,%3};"
                        : "+f"(d[0]), "+f"(d[1]), "+f"(d[2]), "+f"(d[3])
                        : "r"(a0), "r"(a1), "r"(a2), "r"(a3),
                          "r"(bfr[ni][0]), "r"(bfr[ni][1]));
                }
            }
        }

        buf++;
        if (buf == STAGES) buf = 0;
    }

    // Epilogue: bias + ReLU -> fp16
    #pragma unroll
    for (int mi = 0; mi < 4; mi++) {
        int row0 = m0 + wm + mi * 16 + g;
        #pragma unroll
        for (int ni = 0; ni < 8; ni++) {
            int col = n0 + wn + ni * 8 + t4 * 2;
            float bb0 = bias[col], bb1 = bias[col + 1];
            float v0 = fmaxf(acc[mi][ni][0] + bb0, 0.f);
            float v1 = fmaxf(acc[mi][ni][1] + bb1, 0.f);
            float v2 = fmaxf(acc[mi][ni][2] + bb0, 0.f);
            float v3 = fmaxf(acc[mi][ni][3] + bb1, 0.f);
            *(uint32_t*)(C + (size_t)row0 * N + col)       = packf2(v0, v1);
            *(uint32_t*)(C + (size_t)(row0 + 8) * N + col) = packf2(v2, v3);
        }
    }
}

// ===========================================================================
// GEMM2: h2 = relu( h1 @ W2h^T + b2 ), fp16 out. Exact R15 kernel (20.8us).
// ===========================================================================
__global__ void __launch_bounds__(256, 1) gemm2_f16(
    const __half* __restrict__ A, const __half* __restrict__ Bw,
    const float* __restrict__ bias, __half* __restrict__ C)
{
    constexpr int BM = 128, BN = 256, BK = 64, STAGES = 4;
    constexpr int K = HID, N = HID;
    constexpr int KT = K / BK;                  // 8
    constexpr int SKA = BK + 8;
    constexpr int SKB = BK + 8;
    constexpr int STAGE_H = BM * SKA + BN * SKB;

    extern __shared__ __half smemh[];

    const int tid  = threadIdx.x;
    const int warp = tid >> 5;
    const int lane = tid & 31;
    const int g    = lane >> 2;
    const int t4   = lane & 3;

    const int m0 = blockIdx.y * BM;
    const int n0 = blockIdx.x * BN;
    const int wm = (warp & 1) * 64;
    const int wn = (warp >> 1) * 64;

    float acc[4][8][4];
    #pragma unroll
    for (int i = 0; i < 4; i++)
        #pragma unroll
        for (int j = 0; j < 8; j++)
            #pragma unroll
            for (int k = 0; k < 4; k++) acc[i][j][k] = 0.f;

    auto load_stage = [&](int s, int k0) {
        __half* As = smemh + s * STAGE_H;
        __half* Bs = As + BM * SKA;
        #pragma unroll
        for (int i = 0; i < 4; i++) {
            int q = tid + i * 256;
            int row = q >> 3, c = q & 7;
            cp_async16((uint32_t)__cvta_generic_to_shared(As + row * SKA + c * 8),
                       A + (size_t)(m0 + row) * K + k0 + c * 8);
        }
        #pragma unroll
        for (int i = 0; i < 8; i++) {
            int q = tid + i * 256;
            int row = q >> 3, c = q & 7;
            cp_async16((uint32_t)__cvta_generic_to_shared(Bs + row * SKB + c * 8),
                       Bw + (size_t)(n0 + row) * K + k0 + c * 8);
        }
    };

    #pragma unroll
    for (int s = 0; s < STAGES - 1; s++) {
        load_stage(s, s * BK);
        cp_commit();
    }

    int buf = 0;
    for (int kt = 0; kt < KT; kt++) {
        asm volatile("cp.async.wait_group %0;" :: "n"(STAGES - 2));
        __syncthreads();

        int kn = kt + STAGES - 1;
        if (kn < KT) load_stage(kn % STAGES, kn * BK);
        cp_commit();

        const __half* As = smemh + buf * STAGE_H;
        const __half* Bs = As + BM * SKA;

        #pragma unroll
        for (int kk = 0; kk < BK / 16; kk++) {
            uint32_t b[8][2];
            #pragma unroll
            for (int ni = 0; ni < 8; ni++) {
                const __half* bp = Bs + (wn + ni * 8 + g) * SKB + kk * 16 + t4 * 2;
                b[ni][0] = *(const uint32_t*)bp;
                b[ni][1] = *(const uint32_t*)(bp + 8);
            }
            #pragma unroll
            for (int mi = 0; mi < 4; mi++) {
                const __half* ap  = As + (wm + mi * 16 + g) * SKA + kk * 16 + t4 * 2;
                const __half* ap8 = ap + 8 * SKA;
                uint32_t a0 = *(const uint32_t*)ap;
                uint32_t a1 = *(const uint32_t*)ap8;
                uint32_t a2 = *(const uint32_t*)(ap + 8);
                uint32_t a3 = *(const uint32_t*)(ap8 + 8);
                #pragma unroll
                for (int ni = 0; ni < 8; ni++) {
                    float* d = acc[mi][ni];
                    asm volatile(
                        "mma.sync.aligned.m16n8k16.row.col.f32.f16.f16.f32 "
                        "{%0,%1,%2,%3}, {%4,%5,%6,%7}, {%8,%9}, {%0,%1,%2,%3};"
                        : "+f"(d[0]), "+f"(d[1]), "+f"(d[2]), "+f"(d[3])
                        : "r"(a0), "r"(a1), "r"(a2), "r"(a3),
                          "r"(b[ni][0]), "r"(b[ni][1]));
                }
            }
        }

        buf++;
        if (buf == STAGES) buf = 0;
    }

    #pragma unroll
    for (int mi = 0; mi < 4; mi++) {
        int row0 = m0 + wm + mi * 16 + g;
        #pragma unroll
        for (int ni = 0; ni < 8; ni++) {
            int col = n0 + wn + ni * 8 + t4 * 2;
            float bb0 = bias[col], bb1 = bias[col + 1];
            float v0 = fmaxf(acc[mi][ni][0] + bb0, 0.f);
            float v1 = fmaxf(acc[mi][ni][1] + bb1, 0.f);
            float v2 = fmaxf(acc[mi][ni][2] + bb0, 0.f);
            float v3 = fmaxf(acc[mi][ni][3] + bb1, 0.f);
            *(uint32_t*)(C + (size_t)row0 * N + col)       = packf2(v0, v1);
            *(uint32_t*)(C + (size_t)(row0 + 8) * N + col) = packf2(v2, v3);
        }
    }
}

// ---------------------------------------------------------------------------
// Head: shared = h2 @ W3^T + b3 (N=4), then per-scene routed 2x2 transforms.
// ---------------------------------------------------------------------------
__global__ void head_kernel(const __half* __restrict__ h2,
                            const float* __restrict__ W3,
                            const float* __restrict__ b3,
                            const void* __restrict__ sidx,
                            const float* __restrict__ xyW,
                            const float* __restrict__ xyb,
                            const float* __restrict__ tW,
                            float* __restrict__ out)
{
    const int warp = threadIdx.x >> 5;
    const int lane = threadIdx.x & 31;
    const int row  = blockIdx.x * (blockDim.x >> 5) + warp;

    const uint4* hp = (const uint4*)(h2 + (size_t)row * HID);
    float acc[4] = {0.f, 0.f, 0.f, 0.f};
    #pragma unroll
    for (int j = 0; j < 2; j++) {
        int idx = lane + 32 * j;
        uint4 hv = hp[idx];
        float2 f0 = __half22float2(*(__half2*)&hv.x);
        float2 f1 = __half22float2(*(__half2*)&hv.y);
        float2 f2 = __half22float2(*(__half2*)&hv.z);
        float2 f3 = __half22float2(*(__half2*)&hv.w);
        #pragma unroll
        for (int r = 0; r < 4; r++) {
            const float4* wr = (const float4*)(W3 + r * HID);
            float4 w0 = wr[2 * idx];
            float4 w1 = wr[2 * idx + 1];
            acc[r] += f0.x * w0.x + f0.y * w0.y + f1.x * w0.z + f1.y * w0.w
                    + f2.x * w1.x + f2.y * w1.y + f3.x * w1.z + f3.y * w1.w;
        }
    }
    #pragma unroll
    for (int r = 0; r < 4; r++)
        #pragma unroll
        for (int off = 16; off > 0; off >>= 1)
            acc[r] += __shfl_xor_sync(0xffffffffu, acc[r], off);

    if (lane == 0) {
        float s0 = acc[0] + b3[0];
        float s1 = acc[1] + b3[1];
        float s2 = acc[2] + b3[2];
        float s3 = acc[3] + b3[3];

        int s;
        if (g_idx64) s = (int)((const long long*)sidx)[row];
        else         s = ((const int*)sidx)[row];

        const float* wxy = xyW + s * 4;
        const float* wt  = tW  + s * 4;
        float o0 = wxy[0] * s0 + wxy[1] * s1 + xyb[s * 2 + 0];
        float o1 = wxy[2] * s0 + wxy[3] * s1 + xyb[s * 2 + 1];
        float o2 = wt[0] * s2 + wt[1] * s3;
        float o3 = wt[2] * s2 + wt[3] * s3;
        *(float4*)(out + (size_t)row * 4) = make_float4(o0, o1, o2, o3);
    }
}

// ---------------------------------------------------------------------------
// launch
// ---------------------------------------------------------------------------
extern "C" void kernel_launch(void* const* d_in, const int* in_sizes, int n_in,
                              void* d_out, int out_size)
{
    const float* feat = (const float*)d_in[0];
    const void*  sidx = d_in[1];
    const float* W1   = (const float*)d_in[2];
    const float* b1   = (const float*)d_in[3];
    const float* W2   = (const float*)d_in[4];
    const float* b2   = (const float*)d_in[5];
    const float* W3   = (const float*)d_in[6];
    const float* b3   = (const float*)d_in[7];
    const float* xyW  = (const float*)d_in[8];
    const float* xyb  = (const float*)d_in[9];
    const float* tW   = (const float*)d_in[10];
    float* out = (float*)d_out;

    __half *w1h, *w2h, *h1, *h2;
    cudaGetSymbolAddress((void**)&w1h, g_w1h);
    cudaGetSymbolAddress((void**)&w2h, g_w2h);
    cudaGetSymbolAddress((void**)&h1, g_h1);
    cudaGetSymbolAddress((void**)&h2, g_h2);

    // Both GEMMs: 4 * (128*72 + 256*72) * 2 = 221,184 B
    constexpr int SMEM_BYTES = 4 * (128 * 72 + 256 * 72) * 2;

    cudaFuncSetAttribute(gemm1_fused,
                         cudaFuncAttributeMaxDynamicSharedMemorySize, SMEM_BYTES);
    cudaFuncSetAttribute(gemm2_f16,
                         cudaFuncAttributeMaxDynamicSharedMemorySize, SMEM_BYTES);

    // Init: weight convert + flag reset + idx-dtype detect (one kernel).
    init_kernel<<<512, 256>>>((const float4*)W1, (uint2*)w1h,
                              (const float4*)W2, (uint2*)w2h,
                              (const int*)sidx);

    // GEMM1 with fused converter CTAs: 20 converters + 128 MMA = 148 CTAs.
    gemm1_fused<<<148, 256, SMEM_BYTES>>>(feat, w1h, b1, h1);

    // GEMM2: relu(h1 @ W2^T + b2) -> h2 (fp16)
    gemm2_f16<<<dim3(2, 64), 256, SMEM_BYTES>>>(h1, w2h, b2, h2);

    // Head
    head_kernel<<<B_ROWS / 8, 256>>>(h2, W3, b3, sidx, xyW, xyb, tW, out);
}

// round 17
// speedup vs baseline: 1.0978x; 1.0978x over previous
#include <cuda_runtime.h>
#include <cuda_fp16.h>
#include <cstdint>
#include <cstddef>

// Problem constants
#define B_ROWS 8192
#define FEAT   7680
#define HID    512
#define KT1    (FEAT / 64)      // 120 K-slabs for GEMM1

// Scratch (allocation-free: __device__ globals)
__device__ __half g_feat16[(size_t)B_ROWS * FEAT];   // 126 MB (converted feat)
__device__ __half g_w1h[(size_t)HID * FEAT];         // 7.9 MB
__device__ __half g_w2h[(size_t)HID * HID];          // 0.5 MB
__device__ __half g_h1[(size_t)B_ROWS * HID];        // 8.4 MB
__device__ __half g_h2[(size_t)B_ROWS * HID];        // 8.4 MB
__device__ int    g_idx64;
__device__ int    g_cnt[KT1];                        // slab ready counters

// ---------------------------------------------------------------------------
// helpers
// ---------------------------------------------------------------------------
__device__ __forceinline__ void cp_async16(uint32_t smem_dst, const void* gptr) {
    asm volatile("cp.async.cg.shared.global [%0], [%1], 16;"
                 :: "r"(smem_dst), "l"(gptr));
}
__device__ __forceinline__ void cp_commit() {
    asm volatile("cp.async.commit_group;");
}
__device__ __forceinline__ uint32_t packf2(float x, float y) {
    __half2 h = __floats2half2_rn(x, y);
    return *(uint32_t*)&h;
}

// ---------------------------------------------------------------------------
// Init kernel: convert W1/W2 to fp16, reset slab counters, detect idx dtype.
// Runs before gemm1 on the same stream -> ordering guaranteed every replay.
// ---------------------------------------------------------------------------
__device__ __forceinline__ void cvt_range(const float4* __restrict__ in,
                                          uint2* __restrict__ out, int n4,
                                          int gtid, int stride)
{
    for (int i = gtid; i < n4; i += stride) {
        float4 v = in[i];
        uint2 u;
        u.x = packf2(v.x, v.y);
        u.y = packf2(v.z, v.w);
        out[i] = u;
    }
}

__global__ void init_kernel(const float4* __restrict__ w1, uint2* __restrict__ w1_o,
                            const float4* __restrict__ w2, uint2* __restrict__ w2_o,
                            const int* __restrict__ sidx_raw)
{
    const int gtid   = blockIdx.x * blockDim.x + threadIdx.x;
    const int stride = gridDim.x * blockDim.x;
    if (gtid < KT1) g_cnt[gtid] = 0;
    if (gtid == 0) {
        // int64 values in [0,72) -> every odd 32-bit word is 0.
        int acc = 0;
        #pragma unroll
        for (int i = 0; i < 64; i++) acc |= sidx_raw[2 * i + 1];
        g_idx64 = (acc == 0) ? 1 : 0;
    }
    cvt_range(w1, w1_o, (HID * FEAT) / 4, gtid, stride);
    cvt_range(w2, w2_o, (HID * HID) / 4,  gtid, stride);
}

// ===========================================================================
// GEMM1 (cooperative fused converter): h1 = relu( feat @ W1h^T + b1 ).
// 128 CTAs; each is BOTH a converter and an MMA worker.
//   Convert: CTA c owns rows [64c, 64c+64) of every K-slab. At iteration kt
//   it STGs slab kt+7 (regs loaded at kt-1 -- DRAM latency hidden under the
//   MMA section) and issues LDGs for slab kt+8. Publication: threadfence +
//   atomicAdd(g_cnt[j]); readiness = cnt[j]==128 (leader poll + barrier).
//   MMA: the exact R10/R15 roofline loop (CTA 128x256x64, warp 64x64, STG=4).
// Deadlock-free: wait(flag[kt+3]) only needs all CTAs past iteration kt-4;
// their waits regress strictly to the unconditional prologue (slabs 0..6).
// All 128 CTAs co-resident (occ 1, 128 < 148 SMs).
// ===========================================================================
__global__ void __launch_bounds__(256, 1) gemm1_fused(
    const float* __restrict__ feat, const __half* __restrict__ Bw,
    const float* __restrict__ bias, __half* __restrict__ C)
{
    constexpr int BM = 128, BN = 256, BK = 64, STAGES = 4;
    constexpr int K = FEAT, N = HID, KT = KT1;
    constexpr int SKA = BK + 8;
    constexpr int SKB = BK + 8;
    constexpr int STAGE_H = BM * SKA + BN * SKB;

    extern __shared__ __half smemh[];

    const int tid  = threadIdx.x;
    const int cta  = blockIdx.x;           // 0..127
    const int warp = tid >> 5;
    const int lane = tid & 31;
    const int g    = lane >> 2;
    const int t4   = lane & 3;

    const int m0 = (cta >> 1) * BM;
    const int n0 = (cta & 1) * BN;
    const int wm = (warp & 1) * 64;
    const int wn = (warp >> 1) * 64;

    // Convert-share addressing: CTA owns rows [64*cta, 64*cta+64); each
    // thread owns 4 16B chunks of each slab.
    const int crow   = cta * 64 + (tid >> 4);      // thread's first row (stride 16 rows per 256 q)
    const int cchunk = tid & 15;                   // 16B chunk within row

    auto ldg_share = [&](int j, float4* creg) {
        const size_t colbase = (size_t)j * 64;
        #pragma unroll
        for (int i = 0; i < 4; i++) {
            int row = crow + i * 16;
            creg[i] = *((const float4*)(feat + (size_t)row * FEAT + colbase) + cchunk);
        }
    };
    auto stg_share = [&](int j, const float4* creg) {
        const size_t colbase = (size_t)j * 64;
        #pragma unroll
        for (int i = 0; i < 4; i++) {
            int row = crow + i * 16;
            uint2 u;
            u.x = packf2(creg[i].x, creg[i].y);
            u.y = packf2(creg[i].z, creg[i].w);
            *(uint2*)(g_feat16 + (size_t)row * FEAT + colbase + cchunk * 4) = u;
        }
    };

    float acc[4][8][4];
    #pragma unroll
    for (int i = 0; i < 4; i++)
        #pragma unroll
        for (int j = 0; j < 8; j++)
            #pragma unroll
            for (int k = 0; k < 4; k++) acc[i][j][k] = 0.f;

    const __half* A = g_feat16;

    auto load_stage = [&](int s, int k0) {
        __half* As = smemh + s * STAGE_H;
        __half* Bs = As + BM * SKA;
        #pragma unroll
        for (int i = 0; i < 4; i++) {
            int q = tid + i * 256;
            int row = q >> 3, c = q & 7;
            cp_async16((uint32_t)__cvta_generic_to_shared(As + row * SKA + c * 8),
                       A + (size_t)(m0 + row) * K + k0 + c * 8);
        }
        #pragma unroll
        for (int i = 0; i < 8; i++) {
            int q = tid + i * 256;
            int row = q >> 3, c = q & 7;
            cp_async16((uint32_t)__cvta_generic_to_shared(Bs + row * SKB + c * 8),
                       Bw + (size_t)(n0 + row) * K + k0 + c * 8);
        }
    };

    // ---- prologue: convert slabs 0..6 directly, publish; preload slab 7 ----
    float4 creg[4];
    #pragma unroll
    for (int j = 0; j < 7; j++) {
        ldg_share(j, creg);
        stg_share(j, creg);
    }
    __threadfence();
    __syncthreads();
    if (tid == 0) {
        #pragma unroll
        for (int j = 0; j < 7; j++) atomicAdd(&g_cnt[j], 1);
    }
    ldg_share(7, creg);    // stored at iteration 0

    // Initial pipeline fill (slabs 0..2 are prologue-published; still poll).
    #pragma unroll
    for (int s = 0; s < STAGES - 1; s++) {
        if (tid == 0) {
            while (((volatile int*)g_cnt)[s] != 128) __nanosleep(64);
            __threadfence();
        }
        __syncthreads();
        load_stage(s, s * BK);
        cp_commit();
    }

    int buf = 0;
    for (int kt = 0; kt < KT; kt++) {
        asm volatile("cp.async.wait_group %0;" :: "n"(STAGES - 2));
        __syncthreads();

        // ---- converter drain/refill (pipelined one iteration ahead) ----
        if (kt + 7 < KT) stg_share(kt + 7, creg);
        __threadfence();
        __syncthreads();   // all STGs of slab kt+7 done CTA-wide
        const int kn = kt + STAGES - 1;
        if (tid == 0) {
            if (kt + 7 < KT) atomicAdd(&g_cnt[kt + 7], 1);
            if (kn < KT) {
                while (((volatile int*)g_cnt)[kn] != 128) __nanosleep(64);
                __threadfence();
            }
        }
        if (kt + 8 < KT) ldg_share(kt + 8, creg);   // latency hides under MMA
        __syncthreads();   // flag[kn] seen -> safe to cp.async slab kn

        if (kn < KT) load_stage(kn % STAGES, kn * BK);
        cp_commit();

        const __half* As = smemh + buf * STAGE_H;
        const __half* Bs = As + BM * SKA;

        #pragma unroll
        for (int kk = 0; kk < BK / 16; kk++) {
            uint32_t bfr[8][2];
            #pragma unroll
            for (int ni = 0; ni < 8; ni++) {
                const __half* bp = Bs + (wn + ni * 8 + g) * SKB + kk * 16 + t4 * 2;
                bfr[ni][0] = *(const uint32_t*)bp;
                bfr[ni][1] = *(const uint32_t*)(bp + 8);
            }
            #pragma unroll
            for (int mi = 0; mi < 4; mi++) {
                const __half* ap  = As + (wm + mi * 16 + g) * SKA + kk * 16 + t4 * 2;
                const __half* ap8 = ap + 8 * SKA;
                uint32_t a0 = *(const uint32_t*)ap;
                uint32_t a1 = *(const uint32_t*)ap8;
                uint32_t a2 = *(const uint32_t*)(ap + 8);
                uint32_t a3 = *(const uint32_t*)(ap8 + 8);
                #pragma unroll
                for (int ni = 0; ni < 8; ni++) {
                    float* d = acc[mi][ni];
                    asm volatile(
                        "mma.sync.aligned.m16n8k16.row.col.f32.f16.f16.f32 "
                        "{%0,%1,%2,%3}, {%4,%5,%6,%7}, {%8,%9}, {%0,%1,%2,%3};"
                        : "+f"(d[0]), "+f"(d[1]), "+f"(d[2]), "+f"(d[3])
                        : "r"(a0), "r"(a1), "r"(a2), "r"(a3),
                          "r"(bfr[ni][0]), "r"(bfr[ni][1]));
                }
            }
        }

        buf++;
        if (buf == STAGES) buf = 0;
    }

    // Epilogue: bias + ReLU -> fp16
    #pragma unroll
    for (int mi = 0; mi < 4; mi++) {
        int row0 = m0 + wm + mi * 16 + g;
        #pragma unroll
        for (int ni = 0; ni < 8; ni++) {
            int col = n0 + wn + ni * 8 + t4 * 2;
            float bb0 = bias[col], bb1 = bias[col + 1];
            float v0 = fmaxf(acc[mi][ni][0] + bb0, 0.f);
            float v1 = fmaxf(acc[mi][ni][1] + bb1, 0.f);
            float v2 = fmaxf(acc[mi][ni][2] + bb0, 0.f);
            float v3 = fmaxf(acc[mi][ni][3] + bb1, 0.f);
            *(uint32_t*)(C + (size_t)row0 * N + col)       = packf2(v0, v1);
            *(uint32_t*)(C + (size_t)(row0 + 8) * N + col) = packf2(v2, v3);
        }
    }
}

// ===========================================================================
// GEMM2: h2 = relu( h1 @ W2h^T + b2 ), fp16 out. Exact R15 kernel (20.8us).
// ===========================================================================
__global__ void __launch_bounds__(256, 1) gemm2_f16(
    const __half* __restrict__ A, const __half* __restrict__ Bw,
    const float* __restrict__ bias, __half* __restrict__ C)
{
    constexpr int BM = 128, BN = 256, BK = 64, STAGES = 4;
    constexpr int K = HID, N = HID;
    constexpr int KT = K / BK;                  // 8
    constexpr int SKA = BK + 8;
    constexpr int SKB = BK + 8;
    constexpr int STAGE_H = BM * SKA + BN * SKB;

    extern __shared__ __half smemh[];

    const int tid  = threadIdx.x;
    const int warp = tid >> 5;
    const int lane = tid & 31;
    const int g    = lane >> 2;
    const int t4   = lane & 3;

    const int m0 = blockIdx.y * BM;
    const int n0 = blockIdx.x * BN;
    const int wm = (warp & 1) * 64;
    const int wn = (warp >> 1) * 64;

    float acc[4][8][4];
    #pragma unroll
    for (int i = 0; i < 4; i++)
        #pragma unroll
        for (int j = 0; j < 8; j++)
            #pragma unroll
            for (int k = 0; k < 4; k++) acc[i][j][k] = 0.f;

    auto load_stage = [&](int s, int k0) {
        __half* As = smemh + s * STAGE_H;
        __half* Bs = As + BM * SKA;
        #pragma unroll
        for (int i = 0; i < 4; i++) {
            int q = tid + i * 256;
            int row = q >> 3, c = q & 7;
            cp_async16((uint32_t)__cvta_generic_to_shared(As + row * SKA + c * 8),
                       A + (size_t)(m0 + row) * K + k0 + c * 8);
        }
        #pragma unroll
        for (int i = 0; i < 8; i++) {
            int q = tid + i * 256;
            int row = q >> 3, c = q & 7;
            cp_async16((uint32_t)__cvta_generic_to_shared(Bs + row * SKB + c * 8),
                       Bw + (size_t)(n0 + row) * K + k0 + c * 8);
        }
    };

    #pragma unroll
    for (int s = 0; s < STAGES - 1; s++) {
        load_stage(s, s * BK);
        cp_commit();
    }

    int buf = 0;
    for (int kt = 0; kt < KT; kt++) {
        asm volatile("cp.async.wait_group %0;" :: "n"(STAGES - 2));
        __syncthreads();

        int kn = kt + STAGES - 1;
        if (kn < KT) load_stage(kn % STAGES, kn * BK);
        cp_commit();

        const __half* As = smemh + buf * STAGE_H;
        const __half* Bs = As + BM * SKA;

        #pragma unroll
        for (int kk = 0; kk < BK / 16; kk++) {
            uint32_t b[8][2];
            #pragma unroll
            for (int ni = 0; ni < 8; ni++) {
                const __half* bp = Bs + (wn + ni * 8 + g) * SKB + kk * 16 + t4 * 2;
                b[ni][0] = *(const uint32_t*)bp;
                b[ni][1] = *(const uint32_t*)(bp + 8);
            }
            #pragma unroll
            for (int mi = 0; mi < 4; mi++) {
                const __half* ap  = As + (wm + mi * 16 + g) * SKA + kk * 16 + t4 * 2;
                const __half* ap8 = ap + 8 * SKA;
                uint32_t a0 = *(const uint32_t*)ap;
                uint32_t a1 = *(const uint32_t*)ap8;
                uint32_t a2 = *(const uint32_t*)(ap + 8);
                uint32_t a3 = *(const uint32_t*)(ap8 + 8);
                #pragma unroll
                for (int ni = 0; ni < 8; ni++) {
                    float* d = acc[mi][ni];
                    asm volatile(
                        "mma.sync.aligned.m16n8k16.row.col.f32.f16.f16.f32 "
                        "{%0,%1,%2,%3}, {%4,%5,%6,%7}, {%8,%9}, {%0,%1,%2,%3};"
                        : "+f"(d[0]), "+f"(d[1]), "+f"(d[2]), "+f"(d[3])
                        : "r"(a0), "r"(a1), "r"(a2), "r"(a3),
                          "r"(b[ni][0]), "r"(b[ni][1]));
                }
            }
        }

        buf++;
        if (buf == STAGES) buf = 0;
    }

    #pragma unroll
    for (int mi = 0; mi < 4; mi++) {
        int row0 = m0 + wm + mi * 16 + g;
        #pragma unroll
        for (int ni = 0; ni < 8; ni++) {
            int col = n0 + wn + ni * 8 + t4 * 2;
            float bb0 = bias[col], bb1 = bias[col + 1];
            float v0 = fmaxf(acc[mi][ni][0] + bb0, 0.f);
            float v1 = fmaxf(acc[mi][ni][1] + bb1, 0.f);
            float v2 = fmaxf(acc[mi][ni][2] + bb0, 0.f);
            float v3 = fmaxf(acc[mi][ni][3] + bb1, 0.f);
            *(uint32_t*)(C + (size_t)row0 * N + col)       = packf2(v0, v1);
            *(uint32_t*)(C + (size_t)(row0 + 8) * N + col) = packf2(v2, v3);
        }
    }
}

// ---------------------------------------------------------------------------
// Head: shared = h2 @ W3^T + b3 (N=4), then per-scene routed 2x2 transforms.
// ---------------------------------------------------------------------------
__global__ void head_kernel(const __half* __restrict__ h2,
                            const float* __restrict__ W3,
                            const float* __restrict__ b3,
                            const void* __restrict__ sidx,
                            const float* __restrict__ xyW,
                            const float* __restrict__ xyb,
                            const float* __restrict__ tW,
                            float* __restrict__ out)
{
    const int warp = threadIdx.x >> 5;
    const int lane = threadIdx.x & 31;
    const int row  = blockIdx.x * (blockDim.x >> 5) + warp;

    const uint4* hp = (const uint4*)(h2 + (size_t)row * HID);
    float acc[4] = {0.f, 0.f, 0.f, 0.f};
    #pragma unroll
    for (int j = 0; j < 2; j++) {
        int idx = lane + 32 * j;
        uint4 hv = hp[idx];
        float2 f0 = __half22float2(*(__half2*)&hv.x);
        float2 f1 = __half22float2(*(__half2*)&hv.y);
        float2 f2 = __half22float2(*(__half2*)&hv.z);
        float2 f3 = __half22float2(*(__half2*)&hv.w);
        #pragma unroll
        for (int r = 0; r < 4; r++) {
            const float4* wr = (const float4*)(W3 + r * HID);
            float4 w0 = wr[2 * idx];
            float4 w1 = wr[2 * idx + 1];
            acc[r] += f0.x * w0.x + f0.y * w0.y + f1.x * w0.z + f1.y * w0.w
                    + f2.x * w1.x + f2.y * w1.y + f3.x * w1.z + f3.y * w1.w;
        }
    }
    #pragma unroll
    for (int r = 0; r < 4; r++)
        #pragma unroll
        for (int off = 16; off > 0; off >>= 1)
            acc[r] += __shfl_xor_sync(0xffffffffu, acc[r], off);

    if (lane == 0) {
        float s0 = acc[0] + b3[0];
        float s1 = acc[1] + b3[1];
        float s2 = acc[2] + b3[2];
        float s3 = acc[3] + b3[3];

        int s;
        if (g_idx64) s = (int)((const long long*)sidx)[row];
        else         s = ((const int*)sidx)[row];

        const float* wxy = xyW + s * 4;
        const float* wt  = tW  + s * 4;
        float o0 = wxy[0] * s0 + wxy[1] * s1 + xyb[s * 2 + 0];
        float o1 = wxy[2] * s0 + wxy[3] * s1 + xyb[s * 2 + 1];
        float o2 = wt[0] * s2 + wt[1] * s3;
        float o3 = wt[2] * s2 + wt[3] * s3;
        *(float4*)(out + (size_t)row * 4) = make_float4(o0, o1, o2, o3);
    }
}

// ---------------------------------------------------------------------------
// launch
// ---------------------------------------------------------------------------
extern "C" void kernel_launch(void* const* d_in, const int* in_sizes, int n_in,
                              void* d_out, int out_size)
{
    const float* feat = (const float*)d_in[0];
    const void*  sidx = d_in[1];
    const float* W1   = (const float*)d_in[2];
    const float* b1   = (const float*)d_in[3];
    const float* W2   = (const float*)d_in[4];
    const float* b2   = (const float*)d_in[5];
    const float* W3   = (const float*)d_in[6];
    const float* b3   = (const float*)d_in[7];
    const float* xyW  = (const float*)d_in[8];
    const float* xyb  = (const float*)d_in[9];
    const float* tW   = (const float*)d_in[10];
    float* out = (float*)d_out;

    __half *w1h, *w2h, *h1, *h2;
    cudaGetSymbolAddress((void**)&w1h, g_w1h);
    cudaGetSymbolAddress((void**)&w2h, g_w2h);
    cudaGetSymbolAddress((void**)&h1, g_h1);
    cudaGetSymbolAddress((void**)&h2, g_h2);

    // Both GEMMs: 4 * (128*72 + 256*72) * 2 = 221,184 B
    constexpr int SMEM_BYTES = 4 * (128 * 72 + 256 * 72) * 2;

    cudaFuncSetAttribute(gemm1_fused,
                         cudaFuncAttributeMaxDynamicSharedMemorySize, SMEM_BYTES);
    cudaFuncSetAttribute(gemm2_f16,
                         cudaFuncAttributeMaxDynamicSharedMemorySize, SMEM_BYTES);

    // Init: weight convert + counter reset + idx-dtype detect (one kernel).
    init_kernel<<<512, 256>>>((const float4*)W1, (uint2*)w1h,
                              (const float4*)W2, (uint2*)w2h,
                              (const int*)sidx);

    // GEMM1 with cooperative in-kernel feat conversion: 128 CTAs.
    gemm1_fused<<<128, 256, SMEM_BYTES>>>(feat, w1h, b1, h1);

    // GEMM2: relu(h1 @ W2^T + b2) -> h2 (fp16)
    gemm2_f16<<<dim3(2, 64), 256, SMEM_BYTES>>>(h1, w2h, b2, h2);

    // Head
    head_kernel<<<B_ROWS / 8, 256>>>(h2, W3, b3, sidx, xyW, xyb, tW, out);
}